// round 14
// baseline (speedup 1.0000x reference)
#include <cuda_runtime.h>
#include <cuda_fp16.h>
#include <cuda.h>

#define IN_F  1024
#define OUT_F 1024
#define NG    8
#define BATCH 8192
#define KDIM  9216

typedef unsigned int u32;
typedef unsigned long long u64;

// Device-global scratch (allocation-free contract)
__device__ __half g_Wh[(size_t)OUT_F * KDIM];   // [O][K] 18 MB
__device__ __half g_Fh[(size_t)BATCH * KDIM];   // [B][K] 151 MB
__device__ float  g_S0[(size_t)BATCH * OUT_F];  // 33 MB split-tile partial slot 0 (covers kt=0)
__device__ float  g_S1[(size_t)BATCH * OUT_F];  // 33 MB split-tile partial slot 1

// ============================================================================
// PTX helpers
// ============================================================================
__device__ __forceinline__ u32 smem_u32(const void* p) {
    u32 a;
    asm("{ .reg .u64 t; cvta.to.shared.u64 t, %1; cvt.u32.u64 %0, t; }" : "=r"(a) : "l"(p));
    return a;
}

#define MBAR_INIT(a, n) \
    asm volatile("mbarrier.init.shared.b64 [%0], %1;" :: "r"(a), "r"(n) : "memory")
#define MBAR_EXPECT_TX(a, b) \
    asm volatile("mbarrier.arrive.expect_tx.shared.b64 _, [%0], %1;" :: "r"(a), "r"(b) : "memory")

__device__ __forceinline__ void mbar_wait(u32 mbar, u32 parity) {
    asm volatile(
        "{\n\t.reg .pred P;\n\t"
        "W%=:\n\t"
        "mbarrier.try_wait.parity.acquire.cta.shared::cta.b64 P, [%0], %1, 0x989680;\n\t"
        "@P bra.uni D%=;\n\t"
        "bra.uni W%=;\n\t"
        "D%=:\n\t}"
        :: "r"(mbar), "r"(parity) : "memory");
}

__device__ __forceinline__ void tma_load(u32 dst, const CUtensorMap* m, int cx, int cy, u32 mbar) {
    asm volatile(
        "cp.async.bulk.tensor.3d.shared::cta.global.tile.mbarrier::complete_tx::bytes "
        "[%0], [%1, {%2, %3, %4}], [%5];"
        :: "r"(dst), "l"(m), "r"(cx), "r"(cy), "r"(0), "r"(mbar) : "memory");
}

#define LDSM4(r, addr) \
    asm volatile("ldmatrix.sync.aligned.m8n8.x4.shared.b16 {%0,%1,%2,%3}, [%4];" \
                 : "=r"((r)[0]), "=r"((r)[1]), "=r"((r)[2]), "=r"((r)[3]) : "r"(addr))

#define MMA16816(d, a, b) \
    asm volatile("mma.sync.aligned.m16n8k16.row.col.f32.f16.f16.f32 " \
                 "{%0,%1,%2,%3}, {%4,%5,%6,%7}, {%8,%9}, {%0,%1,%2,%3};" \
                 : "+f"((d)[0]), "+f"((d)[1]), "+f"((d)[2]), "+f"((d)[3]) \
                 : "r"((a)[0]), "r"((a)[1]), "r"((a)[2]), "r"((a)[3]), \
                   "r"((b)[0]), "r"((b)[1]))

// ============================================================================
// Phase A: effective weight W[o][k] in fp16  (k = j*1024 + i)
// ============================================================================
__global__ void build_w_kernel(const float* __restrict__ scale_base,
                               const float* __restrict__ spline_weight,
                               const float* __restrict__ scale_spline) {
    int idx = blockIdx.x * blockDim.x + threadIdx.x;
    if (idx >= IN_F * OUT_F) return;
    int o = idx >> 10;
    int i = idx & 1023;

    float sb = scale_base[(size_t)i * OUT_F + o];
    float ss = scale_spline[(size_t)i * OUT_F + o];
    __half* w = g_Wh + (size_t)o * KDIM;
    w[i] = __float2half_rn(sb);

    const float4* swp = reinterpret_cast<const float4*>(spline_weight + ((size_t)o * IN_F + i) * NG);
    float4 w0 = swp[0];
    float4 w1 = swp[1];
    w[1 * 1024 + i] = __float2half_rn(w0.x * ss);
    w[2 * 1024 + i] = __float2half_rn(w0.y * ss);
    w[3 * 1024 + i] = __float2half_rn(w0.z * ss);
    w[4 * 1024 + i] = __float2half_rn(w0.w * ss);
    w[5 * 1024 + i] = __float2half_rn(w1.x * ss);
    w[6 * 1024 + i] = __float2half_rn(w1.y * ss);
    w[7 * 1024 + i] = __float2half_rn(w1.z * ss);
    w[8 * 1024 + i] = __float2half_rn(w1.w * ss);
}

// ============================================================================
// Phase B: feature matrix F[b][k] in fp16
// ============================================================================
__global__ void build_f_kernel(const float* __restrict__ x,
                               const float* __restrict__ grid,
                               const float* __restrict__ sigma_p) {
    int idx = blockIdx.x * blockDim.x + threadIdx.x;
    if (idx >= BATCH * IN_F) return;
    int b = idx >> 10;
    int i = idx & (IN_F - 1);

    float xv = x[idx];
    float inv_sigma = __fdividef(1.0f, *sigma_p);
    size_t base = (size_t)b * KDIM;

    g_Fh[base + i] = __float2half_rn(__fdividef(xv, 1.0f + __expf(-xv)));  // silu

    const float4* gp = reinterpret_cast<const float4*>(grid + (size_t)i * NG);
    float4 g0 = gp[0];
    float4 g1 = gp[1];
    float gv[NG] = {g0.x, g0.y, g0.z, g0.w, g1.x, g1.y, g1.z, g1.w};
#pragma unroll
    for (int g = 0; g < NG; g++) {
        float t = (xv - gv[g]) * inv_sigma;
        g_Fh[base + (size_t)(1 + g) * IN_F + i] = __float2half_rn(__expf(-t * t));
    }
}

// ============================================================================
// Phase C: balanced persistent k-stream GEMM.
//   Global job u in [0, 36864): tile t = u/144 (brow=(t>>2)*128, bcol=(t&3)*256),
//   k-tile kt = u%144. Worker w = blockIdx takes [S(w), S(w+1)), S(w)=w*NJOB/W.
//   Fully-covered tiles -> C; split tiles -> scratch slot (kt_lo==0 ? S0 : S1).
// ============================================================================
#define BM 128
#define BN 256
#define BK 64
#define NKT (KDIM / BK)           // 144
#define NTILES 256
#define NJOB (NTILES * NKT)       // 36864
#define NSTG 4
#define STG_A 16384
#define STG_B 32768
#define STG_BYTES (STG_A + STG_B) // 49152
#define SM_STAGE0 1024
#define SMEM_TOTAL (SM_STAGE0 + NSTG * STG_BYTES)  // 197632

struct Frag {
    u32 a[4][4];
    u32 b[8][2];
};

__device__ __forceinline__ void load_frags(Frag& f, u32 sA, u32 sB, int ks,
                                           int j, int i8, int wm, int wn,
                                           int arow_in, int nrow_in) {
    const int cA = ks * 2 + (j >> 1);
    const int cB = ks * 2 + (j & 1);
#pragma unroll
    for (int mi = 0; mi < 4; mi++) {
        int ar = wm * 64 + mi * 16 + arow_in;
        LDSM4(f.a[mi], sA + (u32)ar * 128 + (u32)((cA ^ i8) << 4));
    }
#pragma unroll
    for (int p = 0; p < 4; p++) {
        int br = wn * 64 + p * 16 + nrow_in;
        u32 r[4];
        LDSM4(r, sB + (u32)br * 128 + (u32)((cB ^ i8) << 4));
        f.b[2 * p][0] = r[0];     f.b[2 * p][1] = r[1];
        f.b[2 * p + 1][0] = r[2]; f.b[2 * p + 1][1] = r[3];
    }
}

__device__ __forceinline__ u64 Sfun(u32 w, u32 W) {
    return ((u64)w * NJOB) / W;
}
__device__ __forceinline__ void decode(int u, int& kt, int& brow, int& bcol) {
    int t = u / NKT;
    kt = u - t * NKT;
    brow = (t >> 2) << 7;
    bcol = (t & 3) << 8;
}

__device__ __forceinline__ void flush_acc(float acc[4][8][4], float* base,
                                          int brow, int bcol, int wm, int wn, int lane) {
    const int r0 = brow + wm * 64 + (lane >> 2);
    const int c0 = bcol + wn * 64 + 2 * (lane & 3);
#pragma unroll
    for (int mi = 0; mi < 4; mi++) {
#pragma unroll
        for (int ni = 0; ni < 8; ni++) {
            float* p = base + (size_t)(r0 + mi * 16) * OUT_F + c0 + ni * 8;
            *(float2*)p = make_float2(acc[mi][ni][0], acc[mi][ni][1]);
            *(float2*)(p + (size_t)8 * OUT_F) = make_float2(acc[mi][ni][2], acc[mi][ni][3]);
            acc[mi][ni][0] = 0.0f; acc[mi][ni][1] = 0.0f;
            acc[mi][ni][2] = 0.0f; acc[mi][ni][3] = 0.0f;
        }
    }
}

__global__ void __launch_bounds__(256, 1)
gemm_kernel(const __grid_constant__ CUtensorMap tma_a,
            const __grid_constant__ CUtensorMap tma_b,
            float* __restrict__ C) {
    extern __shared__ __align__(1024) char smem[];
    const u32 sbase = smem_u32(smem);
    const int tid = threadIdx.x;
    const int lane = tid & 31;
    const int wid = tid >> 5;
    const int wm = wid & 1;
    const int wn = wid >> 1;
    const u32 W = gridDim.x;
    const int ustart = (int)Sfun(blockIdx.x, W);
    const int uend   = (int)Sfun(blockIdx.x + 1, W);

    if (tid == 0) {
#pragma unroll
        for (int s = 0; s < NSTG; s++) MBAR_INIT(sbase + s * 8, 1);
    }
    __syncthreads();

    // prologue: fill up to 4 stages
    if (tid == 0) {
#pragma unroll
        for (int q = 0; q < NSTG; q++) {
            int un = ustart + q;
            if (un < uend) {
                int kt, br, bc; decode(un, kt, br, bc);
                const u32 full = sbase + (un & 3) * 8;
                const u32 sA = sbase + SM_STAGE0 + (un & 3) * STG_BYTES;
                MBAR_EXPECT_TX(full, STG_BYTES);
                tma_load(sA, &tma_a, kt * BK, br, full);
                tma_load(sA + STG_A, &tma_b, kt * BK, bc, full);
            }
        }
    }

    float acc[4][8][4];
#pragma unroll
    for (int mi = 0; mi < 4; mi++)
#pragma unroll
        for (int ni = 0; ni < 8; ni++)
#pragma unroll
            for (int q = 0; q < 4; q++) acc[mi][ni][q] = 0.0f;

    const int j = lane >> 3;
    const int i8 = lane & 7;
    const int arow_in = (j & 1) * 8 + i8;
    const int nrow_in = (j >> 1) * 8 + i8;

    Frag frag[2];
    u32 ph = 0;   // per-stage phase bits

    {
        const int s0 = ustart & 3;
        mbar_wait(sbase + s0 * 8, (ph >> s0) & 1);
        ph ^= 1u << s0;
        const u32 sA = sbase + SM_STAGE0 + s0 * STG_BYTES;
        load_frags(frag[0], sA, sA + STG_A, 0, j, i8, wm, wn, arow_in, nrow_in);
    }

    for (int u = ustart; u < uend; u++) {
        const int stage = u & 3;
        const u32 sA = sbase + SM_STAGE0 + stage * STG_BYTES;
        const u32 sB = sA + STG_A;
        const int t = u / NKT;

#pragma unroll
        for (int ks = 0; ks < 4; ks++) {
            const int cur = ks & 1;
            const int nxt = cur ^ 1;

            if (ks < 3) {
                load_frags(frag[nxt], sA, sB, ks + 1, j, i8, wm, wn, arow_in, nrow_in);
            } else if (u + 1 < uend) {
                __syncthreads();                 // stage drained by all warps
                if (tid == 0 && u + NSTG < uend) {
                    int kt4, br4, bc4; decode(u + NSTG, kt4, br4, bc4);
                    const u32 full = sbase + ((u + NSTG) & 3) * 8;
                    const u32 sAn = sbase + SM_STAGE0 + ((u + NSTG) & 3) * STG_BYTES;
                    MBAR_EXPECT_TX(full, STG_BYTES);
                    tma_load(sAn, &tma_a, kt4 * BK, br4, full);
                    tma_load(sAn + STG_A, &tma_b, kt4 * BK, bc4, full);
                }
                const int s1 = (u + 1) & 3;
                mbar_wait(sbase + s1 * 8, (ph >> s1) & 1);
                ph ^= 1u << s1;
                const u32 sAn = sbase + SM_STAGE0 + s1 * STG_BYTES;
                load_frags(frag[nxt], sAn, sAn + STG_A, 0, j, i8, wm, wn, arow_in, nrow_in);
            }

#pragma unroll
            for (int mi = 0; mi < 4; mi++)
#pragma unroll
                for (int ni = 0; ni < 8; ni++)
                    MMA16816(acc[mi][ni], frag[cur].a[mi], frag[cur].b[ni]);
        }

        // tile boundary (or worker end): flush accumulator
        if (u + 1 == uend || (u + 1) / NKT != t) {
            const int u0t = t * NKT;
            const int kt_lo = (ustart > u0t) ? (ustart - u0t) : 0;
            const int kt_hi = ((u0t + NKT < uend) ? (u0t + NKT) : uend) - u0t;
            const int brow = (t >> 2) << 7;
            const int bcol = (t & 3) << 8;
            float* dst = (kt_lo == 0 && kt_hi == NKT) ? C : (kt_lo == 0 ? g_S0 : g_S1);
            flush_acc(acc, dst, brow, bcol, wm, wn, lane);
        }
    }
}

// ============================================================================
// Reduction: for split tiles, C = S0 + S1.  grid (256 tiles, 128 rows), 256 thr.
// ============================================================================
__global__ void reduce_kernel(float* __restrict__ C, u32 W) {
    const int t = blockIdx.x;
    const int u0 = t * NKT;
    u32 w = (u32)(((u64)u0 * W) / NJOB);
    while (Sfun(w + 1, W) <= (u64)u0) w++;
    while (Sfun(w, W) > (u64)u0) w--;
    const bool split = (Sfun(w + 1, W) < (u64)(u0 + NKT));
    if (!split) return;
    const int brow = (t >> 2) << 7;
    const int bcol = (t & 3) << 8;
    const size_t idx = (size_t)(brow + blockIdx.y) * OUT_F + bcol + threadIdx.x;
    C[idx] = g_S0[idx] + g_S1[idx];
}

// ============================================================================
// Host side
// ============================================================================
typedef CUresult (*EncodeFn)(CUtensorMap*, CUtensorMapDataType, cuuint32_t, void*,
                             const cuuint64_t*, const cuuint64_t*, const cuuint32_t*,
                             const cuuint32_t*, CUtensorMapInterleave, CUtensorMapSwizzle,
                             CUtensorMapL2promotion, CUtensorMapFloatOOBfill);

static void encode_map(EncodeFn fn, CUtensorMap* m, void* ptr, cuuint64_t rows, cuuint32_t box_rows) {
    cuuint64_t dims[3]    = {KDIM, rows, 1};
    cuuint64_t strides[2] = {(cuuint64_t)KDIM * 2, (cuuint64_t)KDIM * 2 * rows};
    cuuint32_t box[3]     = {BK, box_rows, 1};
    cuuint32_t estr[3]    = {1, 1, 1};
    fn(m, CU_TENSOR_MAP_DATA_TYPE_FLOAT16, 3, ptr, dims, strides, box, estr,
       CU_TENSOR_MAP_INTERLEAVE_NONE, CU_TENSOR_MAP_SWIZZLE_128B,
       CU_TENSOR_MAP_L2_PROMOTION_L2_128B, CU_TENSOR_MAP_FLOAT_OOB_FILL_NONE);
}

extern "C" void kernel_launch(void* const* d_in, const int* in_sizes, int n_in,
                              void* d_out, int out_size) {
    const float* x             = (const float*)d_in[0];
    const float* scale_base    = (const float*)d_in[1];
    const float* spline_weight = (const float*)d_in[2];
    const float* scale_spline  = (const float*)d_in[3];
    const float* grid          = (const float*)d_in[4];
    const float* sigma         = (const float*)d_in[5];
    float* out = (float*)d_out;

    static EncodeFn enc = nullptr;
    if (!enc) {
        void* sym = nullptr;
        cudaDriverEntryPointQueryResult st;
        cudaGetDriverEntryPoint("cuTensorMapEncodeTiled", &sym, cudaEnableDefault, &st);
        enc = (EncodeFn)sym;
    }
    void* pF = nullptr; void* pW = nullptr;
    cudaGetSymbolAddress(&pF, g_Fh);
    cudaGetSymbolAddress(&pW, g_Wh);

    CUtensorMap map_a, map_b;
    encode_map(enc, &map_a, pF, BATCH, 128);
    encode_map(enc, &map_b, pW, OUT_F, 256);

    static int smcount = 0;
    if (!smcount) {
        cudaDeviceGetAttribute(&smcount, cudaDevAttrMultiProcessorCount, 0);
        cudaFuncSetAttribute(gemm_kernel,
                             cudaFuncAttributeMaxDynamicSharedMemorySize, SMEM_TOTAL);
    }

    build_w_kernel<<<(IN_F * OUT_F + 255) / 256, 256>>>(scale_base, spline_weight, scale_spline);
    build_f_kernel<<<(BATCH * IN_F + 255) / 256, 256>>>(x, grid, sigma);
    gemm_kernel<<<smcount, 256, SMEM_TOTAL>>>(map_a, map_b, out);
    reduce_kernel<<<dim3(NTILES, BM), 256>>>(out, (u32)smcount);
}